// round 8
// baseline (speedup 1.0000x reference)
#include <cuda_runtime.h>
#include <cuda_fp16.h>

#define NPTS   100000
#define BATCH  16
#define MNB    9
#define NSLOTS (NPTS * 3)              /* per-batch floats, divisible by 4 */
#define TP     128                     /* points per k_diff tile           */
#define QB     (TP * 3 / 4)            /* 96 float4 slots per batch        */
#define ROWB   128                     /* padded row bytes (data in 96B)   */
#define INV_COUNT (1.0f / (float)(BATCH * NPTS * 3))

/* k_lap geometry: 8 warps/block, 5 pts per warp-iter, 4 iters -> 160 pts/blk */
#define LAP_ITERS   4
#define PTS_PER_IT  5
#define PTS_PER_WARP (LAP_ITERS * PTS_PER_IT)      /* 20  */
#define PTS_PER_BLK (8 * PTS_PER_WARP)             /* 160 */
#define LAP_BLOCKS  (NPTS / PTS_PER_BLK)           /* 625, exact */

// Scratch: d = gt - pr in fp16. Row n at byte n*128; halves [0,48) hold
// value at (c,b) packed as index c*16+b. Bytes [96,128) are padding.
__device__ __half g_dt[NPTS * 64];

// ---------------------------------------------------------------------------
// Kernel 1: diff + transpose (B,N,3) -> padded fp16 rows.  (unchanged, near
// its DRAM-read floor)
// ---------------------------------------------------------------------------
__global__ void k_diff(const float* __restrict__ gt, const float* __restrict__ pr,
                       float* __restrict__ out) {
    if (blockIdx.x == 0 && threadIdx.x == 0) out[0] = 0.0f;

    __shared__ float4 s4[QB * 16];     // 24KB
    const float* sf = (const float*)s4;

    int n0 = blockIdx.x * TP;
    int slot0 = n0 * 3;

    for (int i = threadIdx.x; i < 16 * QB; i += 256) {
        int b = i / QB;
        int q = i - b * QB;
        int slot = slot0 + q * 4;
        float4 v = make_float4(0.f, 0.f, 0.f, 0.f);
        if (slot < NSLOTS) {
            float4 g = *(const float4*)(gt + (size_t)b * NSLOTS + slot);
            float4 p = *(const float4*)(pr + (size_t)b * NSLOTS + slot);
            v = make_float4(g.x - p.x, g.y - p.y, g.z - p.z, g.w - p.w);
        }
        s4[q * 16 + (b ^ (q & 15))] = v;
    }
    __syncthreads();

    int valid = NPTS - n0;
    if (valid > TP) valid = TP;
    int total2 = valid * 24;
    __half2* outp = (__half2*)g_dt;
    for (int j = threadIdx.x; j < total2; j += 256) {
        int m   = 2 * j;
        int r   = m >> 4;
        int b0  = m & 15;
        int q   = r >> 2;
        int cmp = r & 3;
        float f0 = sf[4 * (q * 16 + (b0       ^ (q & 15))) + cmp];
        float f1 = sf[4 * (q * 16 + ((b0 + 1) ^ (q & 15))) + cmp];
        int p = r / 3, c = r - 3 * p;
        int hidx = (n0 + p) * 64 + c * 16 + b0;
        outp[hidx >> 1] = __floats2half2_rn(f0, f1);
    }
}

// ---------------------------------------------------------------------------
// Kernel 2: gather laplacian. Block stages 160 points' ids+num in smem
// (coalesced), then each warp loops 4x over groups of 5 points:
// 6 lanes/point, lane owns one line-aligned 16B chunk of the 128B row,
// 9 uint4 gathers kept fully in flight (regs unconstrained).
// ---------------------------------------------------------------------------
__global__ void k_lap(const int* __restrict__ nb, const float* __restrict__ num,
                      float* __restrict__ out) {
    const unsigned FULL = 0xFFFFFFFFu;
    __shared__ int   s_ids[PTS_PER_BLK * MNB];   // 1440 ints
    __shared__ float s_num[PTS_PER_BLK];
    __shared__ float ws[8];

    int tid  = threadIdx.x;
    int lane = tid & 31;
    int w    = tid >> 5;
    int P0   = blockIdx.x * PTS_PER_BLK;

    // cooperative staging: 1440 ints = 360 int4 (P0*9 = blk*1440, 16B-aligned)
    {
        const int4* nb4 = (const int4*)(nb + (size_t)P0 * MNB);
        int4* sd4 = (int4*)s_ids;
        #pragma unroll
        for (int i = tid; i < PTS_PER_BLK * MNB / 4; i += 256)
            sd4[i] = nb4[i];
        if (tid < PTS_PER_BLK)
            s_num[tid] = num[P0 + tid];
    }
    __syncthreads();

    int g    = lane / 6;                          // point group 0..4 (5: idle)
    int s    = lane - g * 6;                      // chunk 0..5
    bool act = lane < 30;
    int coff = s * 16;
    const char* base = (const char*)g_dt;
    const uint4 z4 = make_uint4(0u, 0u, 0u, 0u);

    float accw = 0.0f;

    #pragma unroll
    for (int it = 0; it < LAP_ITERS; it++) {
        int pl = act ? (w * PTS_PER_WARP + it * PTS_PER_IT + g) : 0;

        int ids[MNB];
        #pragma unroll
        for (int j = 0; j < MNB; j++)
            ids[j] = s_ids[pl * MNB + j];
        float wnum = s_num[pl];

        uint4 v[MNB];
        #pragma unroll
        for (int j = 0; j < MNB; j++)
            v[j] = (act && ids[j] < NPTS)
                 ? *(const uint4*)(base + (size_t)ids[j] * ROWB + coff)
                 : z4;

        // center in fp32
        float c[8];
        {
            const __half2* h = (const __half2*)&v[0];
            #pragma unroll
            for (int k = 0; k < 4; k++) {
                float2 f = __half22float2(h[k]);
                c[2 * k]     = f.x * wnum;
                c[2 * k + 1] = f.y * wnum;
            }
        }

        // neighbors 1..8: two independent half2 chains
        __half2 ha[4], hb[4];
        #pragma unroll
        for (int k = 0; k < 4; k++) { ha[k] = __float2half2_rn(0.0f); hb[k] = ha[k]; }
        #pragma unroll
        for (int j = 1; j < MNB; j += 2) {
            const __half2* h = (const __half2*)&v[j];
            #pragma unroll
            for (int k = 0; k < 4; k++) ha[k] = __hadd2(ha[k], h[k]);
        }
        #pragma unroll
        for (int j = 2; j < MNB; j += 2) {
            const __half2* h = (const __half2*)&v[j];
            #pragma unroll
            for (int k = 0; k < 4; k++) hb[k] = __hadd2(hb[k], h[k]);
        }

        if (act) {
            #pragma unroll
            for (int k = 0; k < 4; k++) {
                float2 fa = __half22float2(ha[k]);
                float2 fb = __half22float2(hb[k]);
                accw += fabsf(c[2 * k]     - fa.x - fb.x)
                      + fabsf(c[2 * k + 1] - fa.y - fb.y);
            }
        }
    }

    // warp reduce (fixed order), block reduce, one atomic per block
    #pragma unroll
    for (int off = 16; off > 0; off >>= 1)
        accw += __shfl_down_sync(FULL, accw, off);

    if (lane == 0) ws[w] = accw;
    __syncthreads();
    if (tid < 8) {
        float x = ws[tid];
        #pragma unroll
        for (int off = 4; off > 0; off >>= 1)
            x += __shfl_down_sync(0xFFu, x, off);
        if (tid == 0)
            atomicAdd(out, x * INV_COUNT);
    }
}

// ---------------------------------------------------------------------------
extern "C" void kernel_launch(void* const* d_in, const int* in_sizes, int n_in,
                              void* d_out, int out_size) {
    const float* gt  = (const float*)d_in[0];   // gt_pc        (B,N,3) f32
    const float* pr  = (const float*)d_in[1];   // predict_pc   (B,N,3) f32
    const int*   nb  = (const int*)  d_in[2];   // neighbor ids (N,9)   i32
    const float* num = (const float*)d_in[3];   // neighbor_num (N,)    f32
    float* out = (float*)d_out;

    int nblk1 = (NPTS + TP - 1) / TP;           // 782
    k_diff<<<nblk1, 256>>>(gt, pr, out);
    k_lap <<<LAP_BLOCKS, 256>>>(nb, num, out);
}